// round 16
// baseline (speedup 1.0000x reference)
#include <cuda_runtime.h>
#include <cuda_bf16.h>
#include <cuda_fp16.h>
#include <cstdint>

#define BATCH   1024
#define TWO_B   2048
#define DFLAT   16384
#define NBLK    16
#define NTILE   136
#define NCTA    272
#define FP8_SCALE 128.f
#define INV_ACC   (1.f / 16384.f)

// ---------------- scratch ----------------
__device__ uint8_t  g_rn[(size_t)TWO_B * DFLAT];     // 32 MB e4m3
__device__ float    g_row[TWO_B];
__device__ float    g_pos[TWO_B];
__device__ uint32_t g_part[NCTA][256][32];           // per-CTA f16x2 partial accs (8.9 MB)
__device__ int      g_tflag[NTILE];
__device__ int      g_done;

// ---------------- helpers ----------------
__device__ __forceinline__ uint32_t smem_u32(const void* p) {
    return (uint32_t)__cvta_generic_to_shared(p);
}
__device__ __forceinline__ void cpasync16(uint32_t s, const void* g) {
    asm volatile("cp.async.ca.shared.global [%0], [%1], 16;\n" :: "r"(s), "l"(g));
}
#define CP_COMMIT() asm volatile("cp.async.commit_group;\n")
#define CP_WAIT(N)  asm volatile("cp.async.wait_group %0;\n" :: "n"(N))

#define LDSM4(r0, r1, r2, r3, a) \
    asm volatile("ldmatrix.sync.aligned.m8n8.x4.shared.b16 {%0,%1,%2,%3}, [%4];" \
                 : "=r"(r0), "=r"(r1), "=r"(r2), "=r"(r3) : "r"(a))

__device__ __forceinline__ void mma16832h(uint32_t* c, const uint32_t* a, uint32_t b0, uint32_t b1) {
    asm volatile(
        "mma.sync.aligned.m16n8k32.row.col.f16.e4m3.e4m3.f16 "
        "{%0,%1}, {%2,%3,%4,%5}, {%6,%7}, {%0,%1};\n"
        : "+r"(c[0]), "+r"(c[1])
        : "r"(a[0]), "r"(a[1]), "r"(a[2]), "r"(a[3]), "r"(b0), "r"(b1));
}

__device__ __forceinline__ uint32_t f2_e4m3x2(float hi, float lo) {
    uint16_t r;
    asm volatile("cvt.rn.satfinite.e4m3x2.f32 %0, %1, %2;" : "=h"(r) : "f"(hi), "f"(lo));
    return (uint32_t)r;
}

// ---------------- kernel 1: fused double normalization -> scaled e4m3 (proven) ----------------
__global__ void __launch_bounds__(128) nrm_kernel(const float* __restrict__ ei,
                                                  const float* __restrict__ ej) {
    const int b = blockIdx.x;
    const float* src = (b < BATCH) ? (ei + (size_t)b * DFLAT)
                                   : (ej + (size_t)(b - BATCH) * DFLAT);
    const int tid = threadIdx.x;
    const int w = tid >> 5, lane = tid & 31;
    const int c4 = lane * 4;
    const int r0 = w * 32;
    if (tid == 0) g_row[b] = 0.f;

    __nv_bfloat162 rbuf[64];
    float4 s4 = make_float4(0.f, 0.f, 0.f, 0.f);
    #pragma unroll
    for (int r = 0; r < 32; r++) {
        float4 v = *(const float4*)&src[(r0 + r) * 128 + c4];
        s4.x += v.x * v.x; s4.y += v.y * v.y;
        s4.z += v.z * v.z; s4.w += v.w * v.w;
        rbuf[2 * r]     = __float22bfloat162_rn(make_float2(v.x, v.y));
        rbuf[2 * r + 1] = __float22bfloat162_rn(make_float2(v.z, v.w));
    }
    __shared__ float4 sred[4][32];
    sred[w][lane] = s4;
    __syncthreads();
    float4 cs;
    {
        float4 a = sred[0][lane], bb = sred[1][lane], c = sred[2][lane], d = sred[3][lane];
        cs = make_float4(a.x + bb.x + c.x + d.x, a.y + bb.y + c.y + d.y,
                         a.z + bb.z + c.z + d.z, a.w + bb.w + c.w + d.w);
    }
    float4 inv = make_float4(1.f / fmaxf(sqrtf(cs.x), 1e-12f),
                             1.f / fmaxf(sqrtf(cs.y), 1e-12f),
                             1.f / fmaxf(sqrtf(cs.z), 1e-12f),
                             1.f / fmaxf(sqrtf(cs.w), 1e-12f));
    float t = cs.x * inv.x * inv.x + cs.y * inv.y * inv.y
            + cs.z * inv.z * inv.z + cs.w * inv.w * inv.w;
    #pragma unroll
    for (int off = 16; off > 0; off >>= 1) t += __shfl_xor_sync(0xFFFFFFFF, t, off);
    const float finv = 1.f / fmaxf(sqrtf(t), 1e-8f);
    const float4 scl = make_float4(inv.x * finv * FP8_SCALE, inv.y * finv * FP8_SCALE,
                                   inv.z * finv * FP8_SCALE, inv.w * finv * FP8_SCALE);

    uint32_t* dst = (uint32_t*)(g_rn + (size_t)b * DFLAT);
    #pragma unroll
    for (int r = 0; r < 32; r++) {
        float2 lo = __bfloat1622float2(rbuf[2 * r]);
        float2 hi = __bfloat1622float2(rbuf[2 * r + 1]);
        uint32_t plo = f2_e4m3x2(lo.y * scl.y, lo.x * scl.x);
        uint32_t phi = f2_e4m3x2(hi.y * scl.w, hi.x * scl.z);
        dst[((r0 + r) * 128 + c4) >> 2] = (phi << 16) | plo;
    }
}

// ---------------- kernel 2: K-split FP8 GEMM pairs; 272 CTAs, 2/SM, 4 warps/SMSP ----------------
// Each CTA: full 128x128 tile, HALF the K range (8192), warp tile 32x64 (ratio 2.67).
// Second finisher of each pair combines partials and runs the fused exp epilogue.
#define BK       128
#define KSTEPS   ((DFLAT / 2) / BK)    // 64
#define A_B      (128 * 128)           // 16 KB
#define B_B      (128 * 128)           // 16 KB
#define STAGE_B  (A_B + B_B)           // 32 KB
#define NSTAGE   3
#define GSMEM    (NSTAGE * STAGE_B)    // 96 KB -> 2 CTAs/SM

__global__ void __launch_bounds__(256, 2) gemm_kernel(float* __restrict__ out) {
    extern __shared__ char sm[];
    const uint32_t sbase = smem_u32(sm);
    const int tid = threadIdx.x;
    const int warp = tid >> 5, lane = tid & 31;
    const int wm = warp >> 1, wn = warp & 1;     // 4x2 warp grid; warp tile 32x64
    const int g = lane >> 2, tig = lane & 3;

    const int tile  = blockIdx.x >> 1;
    const int khalf = blockIdx.x & 1;
    int t = tile, bm = 0;
    while (t >= NBLK - bm) { t -= NBLK - bm; bm++; }
    const int bn = bm + t;
    const bool diag  = (bn == bm);
    const bool ptile = (bn - bm == 8);

    const uint8_t* gA = g_rn + (size_t)(bm * 128) * DFLAT + khalf * (DFLAT / 2);
    const uint8_t* gB = g_rn + (size_t)(bn * 128) * DFLAT + khalf * (DFLAT / 2);

    uint32_t acc[2][8][2];
    #pragma unroll
    for (int mt = 0; mt < 2; mt++)
        #pragma unroll
        for (int nt = 0; nt < 8; nt++)
            acc[mt][nt][0] = acc[mt][nt][1] = 0u;

    auto load_stage = [&](int s, int buf) {
        const uint32_t base = sbase + buf * STAGE_B;
        const int k0 = s * BK;
        #pragma unroll
        for (int i = 0; i < 8; i++) {
            int c = tid + i * 256;
            bool isA = (c < 1024);
            int cc  = isA ? c : (c - 1024);
            int row = cc >> 3;
            int cb  = (cc & 7) * 16;
            uint32_t off = row * 128 + (cb ^ ((row & 7) << 4));
            const uint8_t* src = (isA ? gA : gB) + (size_t)row * DFLAT + k0 + cb;
            cpasync16(base + (isA ? 0 : A_B) + off, src);
        }
    };

    load_stage(0, 0); CP_COMMIT();
    load_stage(1, 1); CP_COMMIT();

    const int lrow = lane & 15;
    const int hi   = (lane >> 4) * 16;
    uint32_t aBase[2], aXr[2], bBase[4], bXr[4];
    #pragma unroll
    for (int mt = 0; mt < 2; mt++) {
        int r = wm * 32 + mt * 16 + lrow;
        aBase[mt] = r * 128;  aXr[mt] = (r & 7) << 4;
    }
    #pragma unroll
    for (int p = 0; p < 4; p++) {
        int r = wn * 64 + p * 16 + lrow;
        bBase[p] = A_B + r * 128;  bXr[p] = (r & 7) << 4;
    }

    uint32_t fA[2][2][4];      // [mt][buf][4]
    uint32_t fB[2][4][4];      // [buf][p][4]

    CP_WAIT(1);                // stage 0 arrived
    __syncthreads();
    #pragma unroll
    for (int mt = 0; mt < 2; mt++)
        LDSM4(fA[mt][0][0], fA[mt][0][1], fA[mt][0][2], fA[mt][0][3],
              sbase + aBase[mt] + (hi ^ aXr[mt]));
    #pragma unroll
    for (int p = 0; p < 4; p++)
        LDSM4(fB[0][p][0], fB[0][p][1], fB[0][p][2], fB[0][p][3],
              sbase + bBase[p] + (hi ^ bXr[p]));

    int cur = 0;
    for (int s = 0; s < KSTEPS; s++) {
        if (s) __syncthreads();            // buffer (cur+2)%3 free to overwrite
        int nx = cur + 1; if (nx == 3) nx = 0;
        int lb = nx + 1;  if (lb == 3) lb = 0;
        if (s + 2 < KSTEPS) load_stage(s + 2, lb);
        CP_COMMIT();

        const uint32_t stg  = sbase + cur * STAGE_B;
        const uint32_t stgN = sbase + nx * STAGE_B;

        #pragma unroll
        for (int ks = 0; ks < 4; ks++) {
            const int fc = ks & 1, fn = fc ^ 1;
            if (ks == 3) CP_WAIT(1);       // guarantees stage s+1 arrived
            if (ks < 3) {
                const int kb = (ks + 1) * 32 + hi;
                #pragma unroll
                for (int mt = 0; mt < 2; mt++)
                    LDSM4(fA[mt][fn][0], fA[mt][fn][1], fA[mt][fn][2], fA[mt][fn][3],
                          stg + aBase[mt] + (kb ^ aXr[mt]));
                #pragma unroll
                for (int p = 0; p < 4; p++)
                    LDSM4(fB[fn][p][0], fB[fn][p][1], fB[fn][p][2], fB[fn][p][3],
                          stg + bBase[p] + (kb ^ bXr[p]));
            } else if (s + 1 < KSTEPS) {
                #pragma unroll
                for (int mt = 0; mt < 2; mt++)
                    LDSM4(fA[mt][fn][0], fA[mt][fn][1], fA[mt][fn][2], fA[mt][fn][3],
                          stgN + aBase[mt] + (hi ^ aXr[mt]));
                #pragma unroll
                for (int p = 0; p < 4; p++)
                    LDSM4(fB[fn][p][0], fB[fn][p][1], fB[fn][p][2], fB[fn][p][3],
                          stgN + bBase[p] + (hi ^ bXr[p]));
            }
            #pragma unroll
            for (int nt = 0; nt < 8; nt++) {
                uint32_t b0 = fB[fc][nt >> 1][nt & 1];
                uint32_t b1 = fB[fc][nt >> 1][(nt & 1) + 2];
                mma16832h(acc[0][nt], fA[0][fc], b0, b1);
                mma16832h(acc[1][nt], fA[1][fc], b0, b1);
            }
        }
        cur = nx;
    }

    // ---- store partial, pair ticket ----
    {
        uint4* dst = (uint4*)&g_part[blockIdx.x][tid][0];
        #pragma unroll
        for (int mt = 0; mt < 2; mt++)
            #pragma unroll
            for (int nt = 0; nt < 8; nt += 2)
                dst[mt * 4 + (nt >> 1)] = make_uint4(acc[mt][nt][0], acc[mt][nt][1],
                                                     acc[mt][nt + 1][0], acc[mt][nt + 1][1]);
    }
    __threadfence();
    __syncthreads();
    __shared__ int sh_order;
    if (tid == 0) sh_order = atomicAdd(&g_tflag[tile], 1);
    __syncthreads();
    if (sh_order == 0) return;             // first finisher: partial stored, done

    // ---- second finisher: combine partials + fused exp epilogue ----
    const uint4* par = (const uint4*)&g_part[blockIdx.x ^ 1][tid][0];
    float rowp[2][2] = {{0.f, 0.f}, {0.f, 0.f}};
    float colp[8][2];
    #pragma unroll
    for (int nt = 0; nt < 8; nt++) colp[nt][0] = colp[nt][1] = 0.f;

    #pragma unroll
    for (int mt = 0; mt < 2; mt++) {
        const int rl = wm * 32 + mt * 16 + g;
        #pragma unroll
        for (int nt = 0; nt < 8; nt++) {
            uint4 pp = par[mt * 4 + (nt >> 1)];
            uint32_t p0 = (nt & 1) ? pp.z : pp.x;
            uint32_t p1 = (nt & 1) ? pp.w : pp.y;
            const int cl = wn * 64 + nt * 8 + tig * 2;
            float2 o01 = __half22float2(*(const __half2*)&acc[mt][nt][0]);
            float2 o23 = __half22float2(*(const __half2*)&acc[mt][nt][1]);
            float2 q01 = __half22float2(*(const __half2*)&p0);
            float2 q23 = __half22float2(*(const __half2*)&p1);
            float v0 = (o01.x + q01.x) * INV_ACC, v1 = (o01.y + q01.y) * INV_ACC;
            float v2 = (o23.x + q23.x) * INV_ACC, v3 = (o23.y + q23.y) * INV_ACC;
            float e0 = __expf(2.f * v0), e1 = __expf(2.f * v1);
            float e2 = __expf(2.f * v2), e3 = __expf(2.f * v3);
            if (diag) {
                if (rl == cl)         e0 = 0.f;
                if (rl == cl + 1)     e1 = 0.f;
                if (rl + 8 == cl)     e2 = 0.f;
                if (rl + 8 == cl + 1) e3 = 0.f;
            }
            if (ptile) {
                int gr = bm * 128 + rl;
                if (rl == cl)         { g_pos[gr]     = v0; g_pos[gr + BATCH]     = v0; }
                if (rl == cl + 1)     { g_pos[gr]     = v1; g_pos[gr + BATCH]     = v1; }
                if (rl + 8 == cl)     { g_pos[gr + 8] = v2; g_pos[gr + 8 + BATCH] = v2; }
                if (rl + 8 == cl + 1) { g_pos[gr + 8] = v3; g_pos[gr + 8 + BATCH] = v3; }
            }
            rowp[mt][0] += e0 + e1;
            rowp[mt][1] += e2 + e3;
            colp[nt][0] += e0 + e2;
            colp[nt][1] += e1 + e3;
        }
    }

    #pragma unroll
    for (int mt = 0; mt < 2; mt++)
        #pragma unroll
        for (int h = 0; h < 2; h++) {
            float v = rowp[mt][h];
            v += __shfl_xor_sync(0xFFFFFFFF, v, 1);
            v += __shfl_xor_sync(0xFFFFFFFF, v, 2);
            if (tig == 0)
                atomicAdd(&g_row[bm * 128 + wm * 32 + mt * 16 + g + h * 8], v);
        }

    if (!diag) {
        #pragma unroll
        for (int nt = 0; nt < 8; nt++)
            #pragma unroll
            for (int q = 0; q < 2; q++) {
                float v = colp[nt][q];
                v += __shfl_xor_sync(0xFFFFFFFF, v, 4);
                v += __shfl_xor_sync(0xFFFFFFFF, v, 8);
                v += __shfl_xor_sync(0xFFFFFFFF, v, 16);
                if (g == 0)
                    atomicAdd(&g_row[bn * 128 + wn * 64 + nt * 8 + tig * 2 + q], v);
            }
    }

    // ---- last-tile ticket: inline final reduction ----
    __threadfence();
    __syncthreads();
    __shared__ int is_last;
    if (tid == 0) is_last = (atomicAdd(&g_done, 1) == NTILE - 1) ? 1 : 0;
    __syncthreads();
    if (is_last) {
        __threadfence();
        if (tid < NTILE) g_tflag[tid] = 0;     // reset pair tickets for next replay
        float s = 0.f;
        #pragma unroll
        for (int k = 0; k < 8; k++) {
            int i = tid + k * 256;
            s += logf(g_row[i]) - 2.f * g_pos[i];
        }
        float* red = (float*)sm;
        red[tid] = s;
        __syncthreads();
        for (int off = 128; off > 0; off >>= 1) {
            if (tid < off) red[tid] += red[tid + off];
            __syncthreads();
        }
        if (tid == 0) {
            out[0] = red[0] / (float)TWO_B;
            g_done = 0;
            __threadfence();
        }
    }
}

// ---------------- launch ----------------
extern "C" void kernel_launch(void* const* d_in, const int* in_sizes, int n_in,
                              void* d_out, int out_size) {
    const float* ei = (const float*)d_in[0];
    const float* ej = (const float*)d_in[1];
    float* out = (float*)d_out;

    cudaFuncSetAttribute(gemm_kernel, cudaFuncAttributeMaxDynamicSharedMemorySize, GSMEM);

    nrm_kernel<<<TWO_B, 128>>>(ei, ej);
    gemm_kernel<<<NCTA, 256, GSMEM>>>(out);
}